// round 1
// baseline (speedup 1.0000x reference)
#include <cuda_runtime.h>
#include <cuda_fp16.h>
#include <stdint.h>

// ---------------------------------------------------------------------------
// SplitNN forward:
//   out1 = x1@W1 + b1 ; sens = max(L1row(out1)) - min(L1row(out1))
//   out1 = (out1 + noise*sens/EPS) * rr_mask
//   out2 = x2@W2 + b2
//   out  = min(out1,out2) @ Ws + bs
// Two-phase: K1 computes gemm1 (+bias), row L1 norms -> global min/max atomics,
// stores gemm1+b1 as fp16 scratch. K2 recombines everything.
// ---------------------------------------------------------------------------

#define BROWS   262144
#define FDIM    160
#define HDIM    128
#define CDIM    10
#define TILE_M  128
#define NTHREADS 256

#define LDA 168           // halfs per x-row in smem (160 + 8 pad)
#define LDW 136           // halfs per W-row in smem (128 + 8 pad)
#define LDSRV 130         // floats per server row in smem
#define A_BYTES (TILE_M * LDA * 2)     // 43008
#define W_BYTES (FDIM * LDW * 2)       // 43520
#define DYN_SMEM (A_BYTES + W_BYTES)   // 86528

// 64 MB fp16 scratch for gemm1+b1 (allocation-free: __device__ global)
__device__ __half g_out1[(size_t)BROWS * HDIM];
__device__ int g_min_bits;
__device__ int g_max_bits;

__global__ void init_minmax() {
    g_min_bits = 0x7f800000;  // +inf  (norms are >= 0, int compare == float compare)
    g_max_bits = 0;           // 0.0f
}

__device__ __forceinline__ uint32_t su32(const void* p) {
    return (uint32_t)__cvta_generic_to_shared(p);
}
__device__ __forceinline__ void ldsm4(uint32_t* r, uint32_t a) {
    asm volatile("ldmatrix.sync.aligned.m8n8.x4.shared.b16 {%0,%1,%2,%3},[%4];"
                 : "=r"(r[0]), "=r"(r[1]), "=r"(r[2]), "=r"(r[3]) : "r"(a));
}
__device__ __forceinline__ void ldsm4t(uint32_t* r, uint32_t a) {
    asm volatile("ldmatrix.sync.aligned.m8n8.x4.trans.shared.b16 {%0,%1,%2,%3},[%4];"
                 : "=r"(r[0]), "=r"(r[1]), "=r"(r[2]), "=r"(r[3]) : "r"(a));
}
__device__ __forceinline__ void mma16816(float* c, const uint32_t* a, const uint32_t* b) {
    asm volatile("mma.sync.aligned.m16n8k16.row.col.f32.f16.f16.f32 "
                 "{%0,%1,%2,%3},{%4,%5,%6,%7},{%8,%9},{%0,%1,%2,%3};"
                 : "+f"(c[0]), "+f"(c[1]), "+f"(c[2]), "+f"(c[3])
                 : "r"(a[0]), "r"(a[1]), "r"(a[2]), "r"(a[3]), "r"(b[0]), "r"(b[1]));
}

// Load x tile [128][160] fp32 -> fp16 smem, and W [160][128] fp32 -> fp16 smem.
__device__ __forceinline__ void load_tiles(const float* __restrict__ x,
                                           const float* __restrict__ W,
                                           __half* sA, __half* sW,
                                           size_t row0, int tid) {
    const float4* xs = reinterpret_cast<const float4*>(x) + row0 * (FDIM / 4);
    #pragma unroll
    for (int i = tid; i < TILE_M * (FDIM / 4); i += NTHREADS) {
        int r = i / (FDIM / 4), c = i % (FDIM / 4);
        float4 v = xs[i];
        *reinterpret_cast<__half2*>(&sA[r * LDA + c * 4])     = __floats2half2_rn(v.x, v.y);
        *reinterpret_cast<__half2*>(&sA[r * LDA + c * 4 + 2]) = __floats2half2_rn(v.z, v.w);
    }
    const float4* ws = reinterpret_cast<const float4*>(W);
    #pragma unroll
    for (int i = tid; i < FDIM * (HDIM / 4); i += NTHREADS) {
        int r = i / (HDIM / 4), c = i % (HDIM / 4);
        float4 v = ws[i];
        *reinterpret_cast<__half2*>(&sW[r * LDW + c * 4])     = __floats2half2_rn(v.x, v.y);
        *reinterpret_cast<__half2*>(&sW[r * LDW + c * 4 + 2]) = __floats2half2_rn(v.z, v.w);
    }
}

// Full K=160 mainloop: acc[mt][nt][4] += A(warp rows) * W
__device__ __forceinline__ void mma_tile(const __half* sA, const __half* sW,
                                         float acc[2][8][4], int lane, int wm, int wn) {
    uint32_t aBase = su32(sA), wBase = su32(sW);
    int lr = lane & 15, lc = lane >> 4;
    #pragma unroll
    for (int kk = 0; kk < FDIM / 16; kk++) {
        uint32_t afr[2][4], bfr[4][4];
        #pragma unroll
        for (int mt = 0; mt < 2; mt++)
            ldsm4(afr[mt], aBase + (uint32_t)(((wm * 32 + mt * 16 + lr) * LDA + kk * 16 + lc * 8) * 2));
        #pragma unroll
        for (int nt2 = 0; nt2 < 4; nt2++)
            ldsm4t(bfr[nt2], wBase + (uint32_t)(((kk * 16 + lr) * LDW + wn * 64 + nt2 * 16 + lc * 8) * 2));
        #pragma unroll
        for (int mt = 0; mt < 2; mt++)
            #pragma unroll
            for (int nt = 0; nt < 8; nt++)
                mma16816(acc[mt][nt], afr[mt], &bfr[nt >> 1][(nt & 1) * 2]);
    }
}

// ---------------- Kernel 1: gemm1 + bias, L1-norm min/max, fp16 scratch -----
__global__ __launch_bounds__(NTHREADS, 2)
void k1_kernel(const float* __restrict__ x1, const float* __restrict__ W1,
               const float* __restrict__ b1) {
    extern __shared__ __align__(16) char dyn[];
    __half* sA = (__half*)dyn;
    __half* sW = (__half*)(dyn + A_BYTES);
    __shared__ float sB1[HDIM];
    __shared__ float sNormP[HDIM][2];
    __shared__ float sRed[4][2];

    int tid = threadIdx.x, lane = tid & 31, warp = tid >> 5;
    int wm = warp >> 1, wn = warp & 1;
    size_t row0 = (size_t)blockIdx.x * TILE_M;

    load_tiles(x1, W1, sA, sW, row0, tid);
    if (tid < HDIM) sB1[tid] = b1[tid];
    __syncthreads();

    float acc[2][8][4];
    #pragma unroll
    for (int a = 0; a < 2; a++)
        #pragma unroll
        for (int b = 0; b < 8; b++)
            #pragma unroll
            for (int c = 0; c < 4; c++) acc[a][b][c] = 0.f;

    mma_tile(sA, sW, acc, lane, wm, wn);

    int qr = lane >> 2, qc = lane & 3;
    #pragma unroll
    for (int mt = 0; mt < 2; mt++) {
        int rl = wm * 32 + mt * 16 + qr;   // local row (lo half)
        float pLo = 0.f, pHi = 0.f;
        #pragma unroll
        for (int nt = 0; nt < 8; nt++) {
            int col = wn * 64 + nt * 8 + qc * 2;
            float* c = acc[mt][nt];
            float v0 = c[0] + sB1[col], v1 = c[1] + sB1[col + 1];
            float v2 = c[2] + sB1[col], v3 = c[3] + sB1[col + 1];
            size_t gl = (row0 + rl) * HDIM + col;
            size_t gh = (row0 + rl + 8) * HDIM + col;
            *reinterpret_cast<__half2*>(&g_out1[gl]) = __floats2half2_rn(v0, v1);
            *reinterpret_cast<__half2*>(&g_out1[gh]) = __floats2half2_rn(v2, v3);
            pLo += fabsf(v0) + fabsf(v1);
            pHi += fabsf(v2) + fabsf(v3);
        }
        pLo += __shfl_xor_sync(0xffffffffu, pLo, 1);
        pLo += __shfl_xor_sync(0xffffffffu, pLo, 2);
        pHi += __shfl_xor_sync(0xffffffffu, pHi, 1);
        pHi += __shfl_xor_sync(0xffffffffu, pHi, 2);
        if (qc == 0) { sNormP[rl][wn] = pLo; sNormP[rl + 8][wn] = pHi; }
    }
    __syncthreads();

    if (tid < HDIM) {
        float v = sNormP[tid][0] + sNormP[tid][1];
        float mn = v, mx = v;
        #pragma unroll
        for (int o = 16; o; o >>= 1) {
            mn = fminf(mn, __shfl_xor_sync(0xffffffffu, mn, o));
            mx = fmaxf(mx, __shfl_xor_sync(0xffffffffu, mx, o));
        }
        if (lane == 0) { sRed[warp][0] = mn; sRed[warp][1] = mx; }
    }
    __syncthreads();
    if (tid == 0) {
        float mn = fminf(fminf(sRed[0][0], sRed[1][0]), fminf(sRed[2][0], sRed[3][0]));
        float mx = fmaxf(fmaxf(sRed[0][1], sRed[1][1]), fmaxf(sRed[2][1], sRed[3][1]));
        atomicMin(&g_min_bits, __float_as_int(mn));
        atomicMax(&g_max_bits, __float_as_int(mx));
    }
}

// ---------------- Kernel 2: gemm2, noise+mask+min, projection to 10 ---------
__global__ __launch_bounds__(NTHREADS, 2)
void k2_kernel(const float* __restrict__ x2, const float* __restrict__ W2,
               const float* __restrict__ b2, const float* __restrict__ Ws,
               const float* __restrict__ bs, const float* __restrict__ noise,
               const float* __restrict__ rr, float* __restrict__ out) {
    extern __shared__ __align__(16) char dyn[];
    __half* sA = (__half*)dyn;
    __half* sW = (__half*)(dyn + A_BYTES);
    float* sServ = (float*)dyn;                // aliased after mma (66560B < 86528B)
    __shared__ float sB2[HDIM];
    __shared__ float sMask[HDIM];
    __shared__ float sWs[HDIM * 12];           // 10 cols padded to 12 (zero pad)
    __shared__ float sBs[CDIM];

    int tid = threadIdx.x, lane = tid & 31, warp = tid >> 5;
    int wm = warp >> 1, wn = warp & 1;
    size_t row0 = (size_t)blockIdx.x * TILE_M;

    load_tiles(x2, W2, sA, sW, row0, tid);
    if (tid < HDIM) {
        sB2[tid] = b2[tid];
        sMask[tid] = (rr[tid] < 0.95f) ? 1.f : 0.f;
    }
    #pragma unroll
    for (int i = tid; i < HDIM * 12; i += NTHREADS) {
        int r = i / 12, c = i % 12;
        sWs[i] = (c < CDIM) ? Ws[r * CDIM + c] : 0.f;
    }
    if (tid < CDIM) sBs[tid] = bs[tid];
    float mul = (__int_as_float(g_max_bits) - __int_as_float(g_min_bits)) * 7.5f; // /EPS, EPS=4/30
    __syncthreads();

    float acc[2][8][4];
    #pragma unroll
    for (int a = 0; a < 2; a++)
        #pragma unroll
        for (int b = 0; b < 8; b++)
            #pragma unroll
            for (int c = 0; c < 4; c++) acc[a][b][c] = 0.f;

    mma_tile(sA, sW, acc, lane, wm, wn);
    __syncthreads();   // everyone done reading sA/sW before aliasing as sServ

    int qr = lane >> 2, qc = lane & 3;
    #pragma unroll
    for (int mt = 0; mt < 2; mt++) {
        int rl = wm * 32 + mt * 16 + qr;
        #pragma unroll
        for (int nt = 0; nt < 8; nt++) {
            int col = wn * 64 + nt * 8 + qc * 2;
            float* c = acc[mt][nt];
            float m0 = sMask[col], m1 = sMask[col + 1];
            float bb0 = sB2[col], bb1 = sB2[col + 1];

            size_t gl = (row0 + rl) * HDIM + col;
            size_t gh = (row0 + rl + 8) * HDIM + col;
            float2 o1l = __half22float2(*reinterpret_cast<const __half2*>(&g_out1[gl]));
            float2 o1h = __half22float2(*reinterpret_cast<const __half2*>(&g_out1[gh]));
            float2 nl = *reinterpret_cast<const float2*>(noise + gl);
            float2 nh = *reinterpret_cast<const float2*>(noise + gh);

            float v10 = (o1l.x + nl.x * mul) * m0;
            float v11 = (o1l.y + nl.y * mul) * m1;
            float v12 = (o1h.x + nh.x * mul) * m0;
            float v13 = (o1h.y + nh.y * mul) * m1;

            sServ[rl * LDSRV + col]           = fminf(v10, c[0] + bb0);
            sServ[rl * LDSRV + col + 1]       = fminf(v11, c[1] + bb1);
            sServ[(rl + 8) * LDSRV + col]     = fminf(v12, c[2] + bb0);
            sServ[(rl + 8) * LDSRV + col + 1] = fminf(v13, c[3] + bb1);
        }
    }
    __syncthreads();

    // projection: 2 threads per row, each covers 64 h, fp32
    int prow = tid >> 1, ph = tid & 1;
    const float* srow = &sServ[prow * LDSRV + ph * 64];
    float p[CDIM];
    #pragma unroll
    for (int c = 0; c < CDIM; c++) p[c] = 0.f;
    #pragma unroll
    for (int h = 0; h < 64; h++) {
        float s = srow[h];
        const float4* w = reinterpret_cast<const float4*>(&sWs[(ph * 64 + h) * 12]);
        float4 w0 = w[0], w1 = w[1];
        float2 w2 = reinterpret_cast<const float2*>(w)[4];
        p[0] += s * w0.x; p[1] += s * w0.y; p[2] += s * w0.z; p[3] += s * w0.w;
        p[4] += s * w1.x; p[5] += s * w1.y; p[6] += s * w1.z; p[7] += s * w1.w;
        p[8] += s * w2.x; p[9] += s * w2.y;
    }
    #pragma unroll
    for (int c = 0; c < CDIM; c++) p[c] += __shfl_xor_sync(0xffffffffu, p[c], 1);
    if (ph == 0) {
        float* o = out + (row0 + prow) * CDIM;
        #pragma unroll
        for (int c = 0; c < CDIM; c++) o[c] = p[c] + sBs[c];
    }
}

// ---------------------------------------------------------------------------
extern "C" void kernel_launch(void* const* d_in, const int* in_sizes, int n_in,
                              void* d_out, int out_size) {
    (void)in_sizes; (void)n_in; (void)out_size;
    const float* x1    = (const float*)d_in[0];
    const float* x2    = (const float*)d_in[1];
    const float* W1    = (const float*)d_in[2];
    const float* b1    = (const float*)d_in[3];
    const float* W2    = (const float*)d_in[4];
    const float* b2    = (const float*)d_in[5];
    const float* Ws    = (const float*)d_in[6];
    const float* bs    = (const float*)d_in[7];
    const float* noise = (const float*)d_in[8];
    const float* rr    = (const float*)d_in[9];
    float* out = (float*)d_out;

    cudaFuncSetAttribute(k1_kernel, cudaFuncAttributeMaxDynamicSharedMemorySize, DYN_SMEM);
    cudaFuncSetAttribute(k2_kernel, cudaFuncAttributeMaxDynamicSharedMemorySize, DYN_SMEM);

    int grid = BROWS / TILE_M;   // 2048
    init_minmax<<<1, 1>>>();
    k1_kernel<<<grid, NTHREADS, DYN_SMEM>>>(x1, W1, b1);
    k2_kernel<<<grid, NTHREADS, DYN_SMEM>>>(x2, W2, b2, Ws, bs, noise, rr, out);
}